// round 7
// baseline (speedup 1.0000x reference)
#include <cuda_runtime.h>
#include <cstdint>

#define BB 1024
#define TT 200
#define EE 128
#define HH 64
#define NTHREADS 256

// ---- prepped weights (built once per launch by prep_kernel) ----
__device__ float4 g_bcF[2048];   // (W0b - W0c) in B-fragment order [k][p][lane]
__device__ float4 g_dF [2048];   // (W0d)       in B-fragment order
__device__ float  g_ac [8192];   // (W0a + W0c) natural [e][h] order

__global__ void prep_kernel(const float* __restrict__ W0) {
    const int i = blockIdx.x * blockDim.x + threadIdx.x;   // 8192 threads
    if (i < 8192) {
        const int e = i >> 6, h = i & 63;
        g_ac[i] = __ldg(W0 + e * 64 + h) + __ldg(W0 + (256 + e) * 64 + h);
    }
    if (i < 2048) {
        const int k = i >> 7;
        const int p = (i >> 5) & 3;
        const int l = i & 31;
        const int g = l >> 2, tg = l & 3;
        const int e0 = k * 8 + tg, e1 = e0 + 4;
        const int h0 = p * 16 + g, h1 = h0 + 8;
        float4 bc, dd;
        bc.x = __ldg(W0 + (128 + e0) * 64 + h0) - __ldg(W0 + (256 + e0) * 64 + h0);
        bc.y = __ldg(W0 + (128 + e1) * 64 + h0) - __ldg(W0 + (256 + e1) * 64 + h0);
        bc.z = __ldg(W0 + (128 + e0) * 64 + h1) - __ldg(W0 + (256 + e0) * 64 + h1);
        bc.w = __ldg(W0 + (128 + e1) * 64 + h1) - __ldg(W0 + (256 + e1) * 64 + h1);
        dd.x = __ldg(W0 + (384 + e0) * 64 + h0);
        dd.y = __ldg(W0 + (384 + e1) * 64 + h0);
        dd.z = __ldg(W0 + (384 + e0) * 64 + h1);
        dd.w = __ldg(W0 + (384 + e1) * 64 + h1);
        g_bcF[i] = bc;
        g_dF[i]  = dd;
    }
}

// ---- smem layout (float offsets) ----
#define SM_Q   0          // 128 floats
#define SM_AW  128        // 64 float2
#define SM_AP  256        // 4*64 partial A
#define SM_BF  512        // float4[16][4][32] = 8192 floats (B fragments)
#define SM_AS  8704       // keys tile: 112 rows * 132 floats (padded)
#define SMEM_FLOATS (8704 + 112*132)
#define SMEM_BYTES  (SMEM_FLOATS * 4)

__device__ __forceinline__ float to_tf32(float x) {
    float r; asm("cvt.rna.tf32.f32 %0, %1;" : "=f"(r) : "f"(x)); return r;
}

__device__ __forceinline__ void mma8(float c[4], const uint32_t a[4],
                                     uint32_t b0, uint32_t b1) {
    asm volatile(
        "mma.sync.aligned.m16n8k8.row.col.f32.tf32.tf32.f32 "
        "{%0,%1,%2,%3}, {%4,%5,%6,%7}, {%8,%9}, {%0,%1,%2,%3};"
        : "+f"(c[0]), "+f"(c[1]), "+f"(c[2]), "+f"(c[3])
        : "r"(a[0]), "r"(a[1]), "r"(a[2]), "r"(a[3]), "r"(b0), "r"(b1));
}

__global__ void __launch_bounds__(NTHREADS, 2)
lau_mma_kernel(const float* __restrict__ query,
               const float* __restrict__ keys,
               const float* __restrict__ b0v,
               const float* __restrict__ W1,
               const float* __restrict__ b1v,
               float* __restrict__ out)
{
    extern __shared__ float sm[];
    float*  q_s = sm + SM_Q;
    float2* aw  = (float2*)(sm + SM_AW);
    float*  ap  = sm + SM_AP;
    float*  bf  = sm + SM_BF;
    float*  as_ = sm + SM_AS;

    const int cta  = blockIdx.x;
    const int b    = cta >> 1;
    const int half = cta & 1;
    const int t0   = half ? 96 : 0;
    const int rows = half ? 104 : 96;   // real key rows this CTA
    const int nblk = half ? 7 : 6;      // m16 blocks
    const int npad = nblk * 16;

    const int tid = threadIdx.x;

    // ---- q ----
    if (tid < EE) q_s[tid] = __ldg(query + (size_t)b * EE + tid);
    __syncthreads();

    // ---- keys -> As (tf32, row pad 132) ----
    const float* kb = keys + ((size_t)b * TT + t0) * EE;
    #pragma unroll 4
    for (int idx = tid; idx < npad * 32; idx += NTHREADS) {
        const int r  = idx >> 5;
        const int c4 = idx & 31;
        float4 v = make_float4(0.f, 0.f, 0.f, 0.f);
        if (r < rows) v = __ldg((const float4*)(kb + r * EE) + c4);
        v.x = to_tf32(v.x); v.y = to_tf32(v.y);
        v.z = to_tf32(v.z); v.w = to_tf32(v.w);
        *(float4*)(as_ + r * 132 + c4 * 4) = v;
    }

    // ---- B fragments from prepped streams: Bf = tf32(bc + q*d) ----
    #pragma unroll 4
    for (int idx = tid; idx < 2048; idx += NTHREADS) {
        const float4 bc = __ldg(g_bcF + idx);
        const float4 dd = __ldg(g_dF  + idx);
        const int e0 = ((idx >> 7) << 3) | (idx & 3);
        const float q0 = q_s[e0], q1 = q_s[e0 + 4];
        float4 v;
        v.x = to_tf32(fmaf(q0, dd.x, bc.x));
        v.y = to_tf32(fmaf(q1, dd.y, bc.y));
        v.z = to_tf32(fmaf(q0, dd.z, bc.z));
        v.w = to_tf32(fmaf(q1, dd.w, bc.w));
        *(float4*)(bf + idx * 4) = v;
    }

    // ---- A partials: A[h] = b0[h] + q . (W0a[:,h] + W0c[:,h]) ----
    {
        const int h = tid & 63;
        const int p = tid >> 6;
        float s = 0.f;
        #pragma unroll 8
        for (int e = p * 32; e < p * 32 + 32; ++e)
            s = fmaf(q_s[e], __ldg(g_ac + e * 64 + h), s);
        ap[p * 64 + h] = s;
    }
    __syncthreads();
    if (tid < HH)
        aw[tid] = make_float2(__ldg(b0v + tid) + ap[tid] + ap[64 + tid]
                              + ap[128 + tid] + ap[192 + tid],
                              __ldg(W1 + tid));
    __syncthreads();

    // ---- compute: two m16 blocks per warp (m32), B regs reused ----
    const int wid = tid >> 5;
    const int lid = tid & 31;
    const int g   = lid >> 2;
    const int tg  = lid & 3;
    const int blk0 = wid * 2;
    const int nb   = nblk - blk0;          // >=2: pair, ==1: single, <=0: idle

    if (nb > 0) {
        const bool two = (nb >= 2);

        float acc0[8][4], acc1[8][4];
        #pragma unroll
        for (int j = 0; j < 8; ++j)
            #pragma unroll
            for (int i = 0; i < 4; ++i) { acc0[j][i] = 0.f; acc1[j][i] = 0.f; }

        const uint32_t* asu = (const uint32_t*)as_;
        const uint32_t* bfu = (const uint32_t*)bf;
        const int rA0 = (blk0 * 16 + g) * 132;
        const int rA1 = rA0 + 16 * 132;

        #pragma unroll
        for (int k = 0; k < 16; ++k) {
            const int col = k * 8 + tg;
            uint32_t a0[4], a1[4];
            a0[0] = asu[rA0 + col];
            a0[1] = asu[rA0 + 8 * 132 + col];
            a0[2] = asu[rA0 + col + 4];
            a0[3] = asu[rA0 + 8 * 132 + col + 4];
            if (two) {
                a1[0] = asu[rA1 + col];
                a1[1] = asu[rA1 + 8 * 132 + col];
                a1[2] = asu[rA1 + col + 4];
                a1[3] = asu[rA1 + 8 * 132 + col + 4];
            }
            #pragma unroll
            for (int p = 0; p < 4; ++p) {
                const uint4 bv = *(const uint4*)(bfu + ((k * 4 + p) * 32 + lid) * 4);
                mma8(acc0[2 * p],     a0, bv.x, bv.y);
                mma8(acc0[2 * p + 1], a0, bv.z, bv.w);
                if (two) {
                    mma8(acc1[2 * p],     a1, bv.x, bv.y);
                    mma8(acc1[2 * p + 1], a1, bv.z, bv.w);
                }
            }
        }

        // ---- fused epilogue (per block) ----
        const float bias1 = __ldg(b1v);
        #pragma unroll
        for (int blk = 0; blk < 2; ++blk) {
            if (blk == 1 && !two) break;
            float (*acc)[4] = (blk == 0) ? acc0 : acc1;
            float s0 = bias1, s1 = bias1;
            #pragma unroll
            for (int j = 0; j < 8; ++j) {
                const int h = j * 8 + 2 * tg;
                const float2 w0 = aw[h];
                const float2 w1 = aw[h + 1];
                s0 = fmaf(fmaxf(acc[j][0] + w0.x, 0.f), w0.y, s0);
                s0 = fmaf(fmaxf(acc[j][1] + w1.x, 0.f), w1.y, s0);
                s1 = fmaf(fmaxf(acc[j][2] + w0.x, 0.f), w0.y, s1);
                s1 = fmaf(fmaxf(acc[j][3] + w1.x, 0.f), w1.y, s1);
            }
            s0 += __shfl_xor_sync(0xffffffffu, s0, 1);
            s0 += __shfl_xor_sync(0xffffffffu, s0, 2);
            s1 += __shfl_xor_sync(0xffffffffu, s1, 1);
            s1 += __shfl_xor_sync(0xffffffffu, s1, 2);
            if (tg == 0) {
                const int t = t0 + (blk0 + blk) * 16 + g;
                if (t < TT)     out[(size_t)b * TT + t]     = s0;
                if (t + 8 < TT) out[(size_t)b * TT + t + 8] = s1;
            }
        }
    }
}

extern "C" void kernel_launch(void* const* d_in, const int* in_sizes, int n_in,
                              void* d_out, int out_size)
{
    const float* query = (const float*)d_in[0];
    const float* keys  = (const float*)d_in[1];
    const float* W0    = (const float*)d_in[2];
    const float* b0    = (const float*)d_in[3];
    const float* W1    = (const float*)d_in[4];
    const float* b1    = (const float*)d_in[5];
    float* out = (float*)d_out;

    cudaFuncSetAttribute(lau_mma_kernel,
                         cudaFuncAttributeMaxDynamicSharedMemorySize, SMEM_BYTES);

    prep_kernel<<<32, 256>>>(W0);
    lau_mma_kernel<<<2 * BB, NTHREADS, SMEM_BYTES>>>(query, keys, b0, W1, b1, out);
}

// round 8
// speedup vs baseline: 1.7129x; 1.7129x over previous
#include <cuda_runtime.h>
#include <cstdint>

#define BB 1024
#define TT 200
#define EE 128
#define HH 64
#define NTHREADS 256

// ---- prepped weights (built once per launch by prep_kernel) ----
__device__ float4 g_bcF[2048];   // (W0b - W0c) in B-fragment order [k][p][lane]
__device__ float4 g_dF [2048];   // (W0d)       in B-fragment order
__device__ float  g_ac [8192];   // (W0a + W0c) natural [e][h] order

__global__ void prep_kernel(const float* __restrict__ W0) {
    const int i = blockIdx.x * blockDim.x + threadIdx.x;   // 8192 threads
    if (i < 8192) {
        const int e = i >> 6, h = i & 63;
        g_ac[i] = __ldg(W0 + e * 64 + h) + __ldg(W0 + (256 + e) * 64 + h);
    }
    if (i < 2048) {
        const int k = i >> 7;
        const int p = (i >> 5) & 3;
        const int l = i & 31;
        const int g = l >> 2, tg = l & 3;
        const int e0 = k * 8 + tg, e1 = e0 + 4;
        const int h0 = p * 16 + g, h1 = h0 + 8;
        float4 bc, dd;
        bc.x = __ldg(W0 + (128 + e0) * 64 + h0) - __ldg(W0 + (256 + e0) * 64 + h0);
        bc.y = __ldg(W0 + (128 + e1) * 64 + h0) - __ldg(W0 + (256 + e1) * 64 + h0);
        bc.z = __ldg(W0 + (128 + e0) * 64 + h1) - __ldg(W0 + (256 + e0) * 64 + h1);
        bc.w = __ldg(W0 + (128 + e1) * 64 + h1) - __ldg(W0 + (256 + e1) * 64 + h1);
        dd.x = __ldg(W0 + (384 + e0) * 64 + h0);
        dd.y = __ldg(W0 + (384 + e1) * 64 + h0);
        dd.z = __ldg(W0 + (384 + e0) * 64 + h1);
        dd.w = __ldg(W0 + (384 + e1) * 64 + h1);
        g_bcF[i] = bc;
        g_dF[i]  = dd;
    }
}

// ---- smem layout (float offsets) ----
#define SM_Q   0          // 128 floats
#define SM_AW  128        // 64 float2
#define SM_AP  256        // 4*64 partial A
#define SM_BF  512        // float4[16][4][32] = 8192 floats (B fragments)
#define SM_AS  8704       // keys tile: 112 rows * 132 floats (padded)
#define SMEM_FLOATS (8704 + 112*132)
#define SMEM_BYTES  (SMEM_FLOATS * 4)

__device__ __forceinline__ uint32_t smem_u32(const void* p) {
    uint32_t a;
    asm("{ .reg .u64 t; cvta.to.shared.u64 t, %1; cvt.u32.u64 %0, t; }" : "=r"(a) : "l"(p));
    return a;
}

__device__ __forceinline__ float to_tf32(float x) {
    float r; asm("cvt.rna.tf32.f32 %0, %1;" : "=f"(r) : "f"(x)); return r;
}

// 16B async copy; src_size=0 -> zero fill
__device__ __forceinline__ void cp16(uint32_t dst, const void* src, int src_size) {
    asm volatile("cp.async.cg.shared.global [%0], [%1], 16, %2;"
                 :: "r"(dst), "l"(src), "r"(src_size) : "memory");
}

__device__ __forceinline__ void mma8(float c[4], const uint32_t a[4],
                                     uint32_t b0, uint32_t b1) {
    asm volatile(
        "mma.sync.aligned.m16n8k8.row.col.f32.tf32.tf32.f32 "
        "{%0,%1,%2,%3}, {%4,%5,%6,%7}, {%8,%9}, {%0,%1,%2,%3};"
        : "+f"(c[0]), "+f"(c[1]), "+f"(c[2]), "+f"(c[3])
        : "r"(a[0]), "r"(a[1]), "r"(a[2]), "r"(a[3]), "r"(b0), "r"(b1));
}

__global__ void __launch_bounds__(NTHREADS, 2)
lau_mma_kernel(const float* __restrict__ query,
               const float* __restrict__ keys,
               const float* __restrict__ b0v,
               const float* __restrict__ W1,
               const float* __restrict__ b1v,
               float* __restrict__ out)
{
    extern __shared__ float sm[];
    float*  q_s = sm + SM_Q;
    float2* aw  = (float2*)(sm + SM_AW);
    float*  ap  = sm + SM_AP;
    float*  bf  = sm + SM_BF;
    float*  as_ = sm + SM_AS;

    const int cta  = blockIdx.x;
    const int b    = cta >> 1;
    const int half = cta & 1;
    const int t0   = half ? 96 : 0;
    const int rows = half ? 104 : 96;   // real key rows this CTA
    const int nblk = half ? 7 : 6;      // m16 blocks
    const int npad = nblk * 16;

    const int tid = threadIdx.x;

    // ---- keys -> As via cp.async (raw f32; tf32 mma truncates in HW) ----
    const float* kb = keys + ((size_t)b * TT + t0) * EE;
    const uint32_t as_base = smem_u32(as_);
    #pragma unroll 4
    for (int idx = tid; idx < npad * 32; idx += NTHREADS) {
        const int r  = idx >> 5;
        const int c4 = idx & 31;
        const int rc = (r < rows) ? r : 0;
        cp16(as_base + (uint32_t)(r * 132 + c4 * 4) * 4,
             (const float4*)(kb + rc * EE) + c4,
             (r < rows) ? 16 : 0);
    }
    asm volatile("cp.async.commit_group;" ::: "memory");

    // ---- q ----
    if (tid < EE) q_s[tid] = __ldg(query + (size_t)b * EE + tid);
    __syncthreads();

    // ---- B fragments from prepped streams: Bf = tf32(bc + q*d) ----
    #pragma unroll 4
    for (int idx = tid; idx < 2048; idx += NTHREADS) {
        const float4 bc = __ldg(g_bcF + idx);
        const float4 dd = __ldg(g_dF  + idx);
        const int e0 = ((idx >> 7) << 3) | (idx & 3);
        const float q0 = q_s[e0], q1 = q_s[e0 + 4];
        float4 v;
        v.x = to_tf32(fmaf(q0, dd.x, bc.x));
        v.y = to_tf32(fmaf(q1, dd.y, bc.y));
        v.z = to_tf32(fmaf(q0, dd.z, bc.z));
        v.w = to_tf32(fmaf(q1, dd.w, bc.w));
        *(float4*)(bf + idx * 4) = v;
    }

    // ---- A partials: A[h] = b0[h] + q . (W0a[:,h] + W0c[:,h]) ----
    {
        const int h = tid & 63;
        const int p = tid >> 6;
        float s = 0.f;
        #pragma unroll 8
        for (int e = p * 32; e < p * 32 + 32; ++e)
            s = fmaf(q_s[e], __ldg(g_ac + e * 64 + h), s);
        ap[p * 64 + h] = s;
    }
    __syncthreads();
    if (tid < HH)
        aw[tid] = make_float2(__ldg(b0v + tid) + ap[tid] + ap[64 + tid]
                              + ap[128 + tid] + ap[192 + tid],
                              __ldg(W1 + tid));

    asm volatile("cp.async.wait_group 0;" ::: "memory");
    __syncthreads();

    // ---- compute: one m16 block per warp ----
    const int wid = tid >> 5;
    const int lid = tid & 31;
    if (wid < nblk) {
        const int g  = lid >> 2;
        const int tg = lid & 3;
        const int m0 = wid * 16;

        float acc[8][4];
        #pragma unroll
        for (int j = 0; j < 8; ++j)
            #pragma unroll
            for (int i = 0; i < 4; ++i) acc[j][i] = 0.f;

        const uint32_t* asu = (const uint32_t*)as_;
        const uint32_t* bfu = (const uint32_t*)bf;
        const int rowA = (m0 + g) * 132;

        #pragma unroll
        for (int k = 0; k < 16; ++k) {
            uint32_t a[4];
            const int col = k * 8 + tg;
            a[0] = asu[rowA + col];
            a[1] = asu[rowA + 8 * 132 + col];
            a[2] = asu[rowA + col + 4];
            a[3] = asu[rowA + 8 * 132 + col + 4];
            #pragma unroll
            for (int p = 0; p < 4; ++p) {
                const uint4 bv = *(const uint4*)(bfu + ((k * 4 + p) * 32 + lid) * 4);
                mma8(acc[2 * p],     a, bv.x, bv.y);
                mma8(acc[2 * p + 1], a, bv.z, bv.w);
            }
        }

        // ---- fused epilogue ----
        const float bias1 = __ldg(b1v);
        float s0 = bias1, s1 = bias1;
        #pragma unroll
        for (int j = 0; j < 8; ++j) {
            const int h = j * 8 + 2 * tg;
            const float2 w0 = aw[h];
            const float2 w1 = aw[h + 1];
            s0 = fmaf(fmaxf(acc[j][0] + w0.x, 0.f), w0.y, s0);
            s0 = fmaf(fmaxf(acc[j][1] + w1.x, 0.f), w1.y, s0);
            s1 = fmaf(fmaxf(acc[j][2] + w0.x, 0.f), w0.y, s1);
            s1 = fmaf(fmaxf(acc[j][3] + w1.x, 0.f), w1.y, s1);
        }
        s0 += __shfl_xor_sync(0xffffffffu, s0, 1);
        s0 += __shfl_xor_sync(0xffffffffu, s0, 2);
        s1 += __shfl_xor_sync(0xffffffffu, s1, 1);
        s1 += __shfl_xor_sync(0xffffffffu, s1, 2);
        if (tg == 0) {
            const int t = t0 + m0 + g;
            if (t < TT)     out[(size_t)b * TT + t]     = s0;
            if (t + 8 < TT) out[(size_t)b * TT + t + 8] = s1;
        }
    }
}

extern "C" void kernel_launch(void* const* d_in, const int* in_sizes, int n_in,
                              void* d_out, int out_size)
{
    const float* query = (const float*)d_in[0];
    const float* keys  = (const float*)d_in[1];
    const float* W0    = (const float*)d_in[2];
    const float* b0    = (const float*)d_in[3];
    const float* W1    = (const float*)d_in[4];
    const float* b1    = (const float*)d_in[5];
    float* out = (float*)d_out;

    cudaFuncSetAttribute(lau_mma_kernel,
                         cudaFuncAttributeMaxDynamicSharedMemorySize, SMEM_BYTES);

    prep_kernel<<<32, 256>>>(W0);
    lau_mma_kernel<<<2 * BB, NTHREADS, SMEM_BYTES>>>(query, keys, b0, W1, b1, out);
}